// round 4
// baseline (speedup 1.0000x reference)
#include <cuda_runtime.h>
#include <math.h>

// Problem constants
#define Sv   512
#define Bv   64
#define FINv 512
#define Hv   512
#define G4   2048   // 4*H

// ---------------------------------------------------------------------------
// Scratch: precomputed input-gate term gx[t][b][col] = x_t[b]·W_ih[col] + bias
// ---------------------------------------------------------------------------
__device__ float g_gx[(size_t)Sv * Bv * G4];

// Per-block arrival flags (zero-initialized at load; values are monotone
// across graph replays, targets derived from the start-of-kernel base).
#define NBLK 128
__device__ unsigned int g_flag[NBLK];

// ---------------------------------------------------------------------------
// Packed fp32x2 helpers (Blackwell FFMA2 path — only reachable via PTX)
// ---------------------------------------------------------------------------
__device__ __forceinline__ void fma2(unsigned long long& acc,
                                     unsigned long long a,
                                     unsigned long long b) {
    asm("fma.rn.f32x2 %0, %1, %2, %0;" : "+l"(acc) : "l"(a), "l"(b));
}
__device__ __forceinline__ float2 unpack2(unsigned long long v) {
    float2 f;
    asm("mov.b64 {%0, %1}, %2;" : "=f"(f.x), "=f"(f.y) : "l"(v));
    return f;
}

__device__ __forceinline__ float fast_sigmoid(float x) {
    return __fdividef(1.f, 1.f + __expf(-x));
}
__device__ __forceinline__ float fast_tanh(float x) {
    return __fdividef(2.f, 1.f + __expf(-2.f * x)) - 1.f;
}

// ===========================================================================
// Phase 1: gx = X[32768,512] @ W_ih^T[512,2048] + (b_ih + b_hh)
// 128x128x16 tile, 256 threads, 8x8 microtile, packed f32x2 FMA.
// A stored DUPLICATED in smem ((a,a) pairs) so a packed broadcast operand is a
// single LDS; B stored n-contiguous so (b_n, b_{n+1}) packs load directly.
// ===========================================================================
#define BM 128
#define BN 128
#define BK 16
#define AROW 260   // floats per k-row of As: 2*128 dup + 4 pad (16B-aligned rows)
#define BROW 132   // floats per k-row of Bs: 128 + 4 pad (16B-aligned rows)

__global__ __launch_bounds__(256, 2) void gemm_x_kernel(
    const float* __restrict__ X,     // [32768][512]  (m = t*64 + b)
    const float* __restrict__ W,     // [2048][512]
    const float* __restrict__ bih,
    const float* __restrict__ bhh)
{
    __shared__ float As[BK * AROW];  // 16.6 KB
    __shared__ float Bs[BK * BROW];  // 8.4 KB

    const int tid = threadIdx.x;
    const int m0  = blockIdx.y * BM;
    const int n0  = blockIdx.x * BN;
    const int tx  = tid & 15;        // n microtile index
    const int ty  = tid >> 4;        // m microtile index
    const int lr  = tid >> 2;        // load row (0..63), +64 second half
    const int lc4 = (tid & 3) * 4;   // load k offset (float4)

    unsigned long long acc2[8][4];   // acc2[i][j2] = (C[m][2j2], C[m][2j2+1])
#pragma unroll
    for (int i = 0; i < 8; i++)
#pragma unroll
        for (int j = 0; j < 4; j++) acc2[i][j] = 0ULL;

    for (int k0 = 0; k0 < FINv; k0 += BK) {
#pragma unroll
        for (int jj = 0; jj < 2; jj++) {
            int r = lr + 64 * jj;
            float4 av = *reinterpret_cast<const float4*>(
                X + (size_t)(m0 + r) * FINv + k0 + lc4);
            reinterpret_cast<float2*>(As + (lc4 + 0) * AROW)[r] = make_float2(av.x, av.x);
            reinterpret_cast<float2*>(As + (lc4 + 1) * AROW)[r] = make_float2(av.y, av.y);
            reinterpret_cast<float2*>(As + (lc4 + 2) * AROW)[r] = make_float2(av.z, av.z);
            reinterpret_cast<float2*>(As + (lc4 + 3) * AROW)[r] = make_float2(av.w, av.w);
            float4 bv = *reinterpret_cast<const float4*>(
                W + (size_t)(n0 + r) * FINv + k0 + lc4);
            Bs[(lc4 + 0) * BROW + r] = bv.x;
            Bs[(lc4 + 1) * BROW + r] = bv.y;
            Bs[(lc4 + 2) * BROW + r] = bv.z;
            Bs[(lc4 + 3) * BROW + r] = bv.w;
        }
        __syncthreads();
#pragma unroll
        for (int k = 0; k < BK; k++) {
            // duplicated a pairs: 4x LDS.128 -> 8 broadcast packs
            const ulonglong2* ad =
                reinterpret_cast<const ulonglong2*>(As + k * AROW + ty * 16);
            ulonglong2 a01 = ad[0], a23 = ad[1], a45 = ad[2], a67 = ad[3];
            unsigned long long ap[8] = {a01.x, a01.y, a23.x, a23.y,
                                        a45.x, a45.y, a67.x, a67.y};
            // b packs along n: 2x LDS.128 -> 4 packs
            const ulonglong2* bd =
                reinterpret_cast<const ulonglong2*>(Bs + k * BROW + tx * 8);
            ulonglong2 b03 = bd[0], b47 = bd[1];
            unsigned long long bp[4] = {b03.x, b03.y, b47.x, b47.y};
#pragma unroll
            for (int i = 0; i < 8; i++)
#pragma unroll
                for (int j = 0; j < 4; j++)
                    fma2(acc2[i][j], ap[i], bp[j]);
        }
        __syncthreads();
    }

    float bsum[8];
#pragma unroll
    for (int j = 0; j < 8; j++) {
        int n = n0 + tx * 8 + j;
        bsum[j] = bih[n] + bhh[n];
    }
#pragma unroll
    for (int i = 0; i < 8; i++) {
        float2 p0 = unpack2(acc2[i][0]);
        float2 p1 = unpack2(acc2[i][1]);
        float2 p2 = unpack2(acc2[i][2]);
        float2 p3 = unpack2(acc2[i][3]);
        size_t row = (size_t)(m0 + ty * 8 + i) * G4 + n0 + tx * 8;
        float4 v0 = make_float4(p0.x + bsum[0], p0.y + bsum[1],
                                p1.x + bsum[2], p1.y + bsum[3]);
        float4 v1 = make_float4(p2.x + bsum[4], p2.y + bsum[5],
                                p3.x + bsum[6], p3.y + bsum[7]);
        *reinterpret_cast<float4*>(&g_gx[row])     = v0;
        *reinterpret_cast<float4*>(&g_gx[row + 4]) = v1;
    }
}

// ===========================================================================
// Phase 2: persistent recurrence kernel. 128 blocks x 128 threads.
// Block bx owns hidden units [4bx, 4bx+4) (16 gate-cols). Split-K=4 across
// warps; each thread: 8 cols x 4 batches x K/4, packed f32x2 accumulation.
// c state lives in registers; flag-array grid barrier; fused reduce+update.
// ===========================================================================
// smem float offsets
#define HROW 516
#define WS_OFF  0
#define WS_SZ   8272         // 15*516+4+512 = 8256, padded
#define HS_OFF  WS_SZ
#define HS_SZ   33072        // 63*516+28+512 = 33048, padded
#define RED_OFF (WS_SZ + HS_SZ)          // 41344
#define RED_SZ  (4 * 16 * 68)            // 4352
#define SM_FLOATS (RED_OFF + RED_SZ)     // 45696 floats = 182784 B

__global__ __launch_bounds__(128, 1) void lstm_rec_kernel(
    const float* __restrict__ whh,   // [2048][512]
    float* __restrict__ out)         // [S*B*H hs][S*B*H cs]
{
    extern __shared__ float sm[];
    float* w_s = sm + WS_OFF;    // col c at c*516 + (c>>3)*4
    float* h_s = sm + HS_OFF;    // batch b at b*516 + (b>>3)*4
    float* red = sm + RED_OFF;   // [4 sk][16 col][68 batch]

    float* hs_out = out;
    float* cs_out = out + (size_t)Sv * Bv * Hv;

    const int tid = threadIdx.x;
    const int u0  = blockIdx.x * 4;

    // W_hh slice: local col c (0..15) -> gate=c>>2, unit=c&3
    for (int i = tid; i < 16 * Hv; i += 128) {
        int c = i >> 9, k = i & (Hv - 1);
        int gr = ((c >> 2) * Hv) + u0 + (c & 3);
        w_s[c * HROW + (c >> 3) * 4 + k] = whh[(size_t)gr * Hv + k];
    }

    // Barrier base: own flag's leftover value (uniform across blocks).
    const unsigned base = *((volatile unsigned*)&g_flag[blockIdx.x]);

    // GEMM mapping: warp = K quarter; lane -> (cgrp, bgrp)
    const int sk   = tid >> 5;          // 0..3
    const int lane = tid & 31;
    const int cgrp = lane & 1;          // cols cgrp*8 .. +8
    const int bgrp = lane >> 1;         // batches bgrp + 16*bj
    const float* wbase = w_s + cgrp * (8 * HROW + 4);
    const int hb0 = bgrp * HROW + (bgrp >> 3) * 4;
    const int k4lo = sk * 32;

    // Elementwise mapping: items tid*2, tid*2+1 -> (u, b); c stays in regs.
    int u_e[2], b_e[2];
#pragma unroll
    for (int r = 0; r < 2; r++) {
        int item = tid * 2 + r;
        u_e[r] = item >> 6;
        b_e[r] = item & 63;
    }
    float cpv[2] = {0.f, 0.f};

    __syncthreads();

    for (int t = 0; t < Sv; t++) {
        // ---- prefetch gx gate terms (independent of barrier) ----
        float gxv[2][4];
        {
            const float* gxt = g_gx + (size_t)t * (Bv * G4);
#pragma unroll
            for (int r = 0; r < 2; r++)
#pragma unroll
                for (int g = 0; g < 4; g++)
                    gxv[r][g] = __ldg(gxt + (size_t)b_e[r] * G4 + g * Hv + u0 + u_e[r]);
        }

        // ---- grid barrier: wait until all blocks finished step t-1 ----
        if (t > 0) {
            const unsigned target = base + (unsigned)t;
            bool ok;
            do {
                unsigned v = *((volatile unsigned*)&g_flag[tid]);
                ok = ((int)(v - target) >= 0);
            } while (!__syncthreads_and(ok));
            __threadfence();
        }

        // ---- stage h(t-1) into smem ----
        if (t == 0) {
            for (int i = tid; i < HS_SZ; i += 128) h_s[i] = 0.f;
        } else {
            const float* hp = hs_out + (size_t)(t - 1) * Bv * Hv;
#pragma unroll 8
            for (int j = 0; j < 64; j++) {
                float4 v = __ldcg(reinterpret_cast<const float4*>(hp + (size_t)j * Hv) + tid);
                *reinterpret_cast<float4*>(h_s + j * HROW + (j >> 3) * 4 + 4 * tid) = v;
            }
        }
        __syncthreads();

        // ---- recurrent GEMM: 8 cols x 4 batches, K quarter, packed f32x2 ----
        unsigned long long acc2[8][4];
#pragma unroll
        for (int j = 0; j < 8; j++)
#pragma unroll
            for (int bj = 0; bj < 4; bj++) acc2[j][bj] = 0ULL;

#pragma unroll 2
        for (int k4 = k4lo; k4 < k4lo + 32; k4++) {
            ulonglong2 wv[8], hv[4];
#pragma unroll
            for (int j = 0; j < 8; j++)
                wv[j] = *reinterpret_cast<const ulonglong2*>(wbase + j * HROW + 4 * k4);
#pragma unroll
            for (int bj = 0; bj < 4; bj++)
                hv[bj] = *reinterpret_cast<const ulonglong2*>(h_s + hb0 + bj * (16 * HROW + 8) + 4 * k4);
#pragma unroll
            for (int j = 0; j < 8; j++)
#pragma unroll
                for (int bj = 0; bj < 4; bj++) {
                    fma2(acc2[j][bj], wv[j].x, hv[bj].x);
                    fma2(acc2[j][bj], wv[j].y, hv[bj].y);
                }
        }

        // ---- write split-K partials ----
#pragma unroll
        for (int j = 0; j < 8; j++)
#pragma unroll
            for (int bj = 0; bj < 4; bj++) {
                float2 p = unpack2(acc2[j][bj]);
                red[(sk * 16 + cgrp * 8 + j) * 68 + bgrp + 16 * bj] = p.x + p.y;
            }
        __syncthreads();

        // ---- fused reduction + LSTM update ----
        float* ht = hs_out + (size_t)t * Bv * Hv;
        float* ct = cs_out + (size_t)t * Bv * Hv;
#pragma unroll
        for (int r = 0; r < 2; r++) {
            int u = u_e[r], b = b_e[r];
            float gate[4];
#pragma unroll
            for (int g = 0; g < 4; g++) {
                int c = g * 4 + u;
                gate[g] = red[(0 * 16 + c) * 68 + b] + red[(1 * 16 + c) * 68 + b]
                        + red[(2 * 16 + c) * 68 + b] + red[(3 * 16 + c) * 68 + b]
                        + gxv[r][g];
            }
            float si = fast_sigmoid(gate[0]);
            float sf = fast_sigmoid(gate[1]);
            float tg = fast_tanh(gate[2]);
            float so = fast_sigmoid(gate[3]);
            float cc = sf * cpv[r] + si * tg;
            cpv[r] = cc;
            float hh = so * fast_tanh(cc);
            __stcg(ht + (size_t)b * Hv + u0 + u, hh);
            __stcg(ct + (size_t)b * Hv + u0 + u, cc);
        }

        // ---- arrive ----
        if (t < Sv - 1) {
            __threadfence();
            __syncthreads();
            if (tid == 0)
                atomicExch(&g_flag[blockIdx.x], base + (unsigned)t + 1u);
        }
    }
}

// ===========================================================================
// Launch
// ===========================================================================
extern "C" void kernel_launch(void* const* d_in, const int* in_sizes, int n_in,
                              void* d_out, int out_size)
{
    const float* seq  = (const float*)d_in[0];   // [512,64,512]
    const float* w_ih = (const float*)d_in[1];   // [2048,512]
    const float* w_hh = (const float*)d_in[2];   // [2048,512]
    const float* b_ih = (const float*)d_in[3];   // [2048]
    const float* b_hh = (const float*)d_in[4];   // [2048]
    float* out = (float*)d_out;

    const int smem_p2 = SM_FLOATS * (int)sizeof(float);  // 182784 B
    cudaFuncSetAttribute(lstm_rec_kernel,
                         cudaFuncAttributeMaxDynamicSharedMemorySize, smem_p2);

    dim3 g1(G4 / BN, (Sv * Bv) / BM);   // (16, 256)
    gemm_x_kernel<<<g1, 256>>>(seq, w_ih, b_ih, b_hh);
    lstm_rec_kernel<<<NBLK, 128, smem_p2>>>(w_hh, out);
}